// round 4
// baseline (speedup 1.0000x reference)
#include <cuda_runtime.h>
#include <math.h>
#include <stdint.h>

// Problem constants: B=4, N=1024, D=1024, H=16, DH=64, layers=3
#define MROWS 4096
#define DIM   1024
#define NSEQ  1024
#define NHEAD 16
#define DH    64
#define NLAYER 3

// ---------------- scratch (device globals; no allocation allowed) ----------
__device__ uint32_t g_xnt[(size_t)MROWS * DIM];            // RMSNorm out (tf32)
__device__ uint32_t g_q[(size_t)MROWS * DIM];              // Q rope+scaled (tf32)
__device__ uint32_t g_pa[(size_t)MROWS * DIM];             // ping (tf32)
__device__ uint32_t g_pb[(size_t)MROWS * DIM];             // pong (tf32)
__device__ uint32_t g_k[NLAYER][(size_t)MROWS * DIM];      // K rope'd (tf32)
__device__ uint32_t g_v[NLAYER][(size_t)MROWS * DIM];      // V (tf32)
__device__ uint32_t g_wq[(size_t)DIM * DIM];               // weights (tf32)
__device__ uint32_t g_wk[NLAYER * (size_t)DIM * DIM];
__device__ uint32_t g_wv[NLAYER * (size_t)DIM * DIM];
__device__ uint32_t g_wo[(size_t)DIM * DIM];
__device__ float g_cos[NSEQ * 32];
__device__ float g_sin[NSEQ * 32];

// ---------------- small helpers ---------------------------------------------
__device__ __forceinline__ uint32_t f2tf(float x) {
    uint32_t r;
    asm("cvt.rna.tf32.f32 %0, %1;" : "=r"(r) : "f"(x));
    return r;
}
__device__ __forceinline__ void mma_tf32(
    float c[4], const uint32_t a[4], const uint32_t b[2])
{
    asm volatile(
        "mma.sync.aligned.m16n8k8.row.col.f32.tf32.tf32.f32 "
        "{%0,%1,%2,%3}, {%4,%5,%6,%7}, {%8,%9}, {%0,%1,%2,%3};\n"
        : "+f"(c[0]), "+f"(c[1]), "+f"(c[2]), "+f"(c[3])
        : "r"(a[0]), "r"(a[1]), "r"(a[2]), "r"(a[3]), "r"(b[0]), "r"(b[1]));
}
__device__ __forceinline__ void cpa(uint32_t d, const void* s) {
    asm volatile("cp.async.cg.shared.global [%0], [%1], 16;\n" :: "r"(d), "l"(s));
}
__device__ __forceinline__ void cpcommit() { asm volatile("cp.async.commit_group;\n" ::); }
__device__ __forceinline__ void cpwait0()  { asm volatile("cp.async.wait_group 0;\n" ::); }
__device__ __forceinline__ void cpwait1()  { asm volatile("cp.async.wait_group 1;\n" ::); }

// ---------------- RoPE tables (fp64, matches reference) --------------------
__global__ void rope_tables_kernel() {
    int idx = blockIdx.x * blockDim.x + threadIdx.x;
    if (idx >= NSEQ * 32) return;
    int pos = idx >> 5;
    int p   = idx & 31;
    double inv = pow(10000.0, -((double)(2 * p)) / (double)DH);
    double a = (double)pos * inv;
    g_cos[idx] = (float)cos(a);
    g_sin[idx] = (float)sin(a);
}

// ---------------- weight -> tf32 convert ------------------------------------
__global__ __launch_bounds__(256) void wconv_kernel(
    const float* __restrict__ s, uint32_t* __restrict__ d, int n4)
{
    int i = blockIdx.x * 256 + threadIdx.x;
    if (i >= n4) return;
    float4 v = ((const float4*)s)[i];
    ((uint4*)d)[i] = make_uint4(f2tf(v.x), f2tf(v.y), f2tf(v.z), f2tf(v.w));
}

// ---------------- RMSNorm -> tf32 -------------------------------------------
__global__ __launch_bounds__(256) void rmsnorm_kernel(
    const float* __restrict__ T, const float* __restrict__ gamma,
    uint32_t* __restrict__ X)
{
    int row = blockIdx.x;
    int tid = threadIdx.x;
    float4 v = ((const float4*)(T + (size_t)row * DIM))[tid];
    float s = v.x * v.x + v.y * v.y + v.z * v.z + v.w * v.w;
    #pragma unroll
    for (int o = 16; o > 0; o >>= 1) s += __shfl_xor_sync(0xffffffffu, s, o);
    __shared__ float ws[8];
    if ((tid & 31) == 0) ws[tid >> 5] = s;
    __syncthreads();
    float tot = 0.f;
    #pragma unroll
    for (int i = 0; i < 8; i++) tot += ws[i];
    float rs = rsqrtf(tot * (1.0f / (float)DIM) + 1.1920929e-07f);
    float4 g = ((const float4*)gamma)[tid];
    ((uint4*)(X + (size_t)row * DIM))[tid] = make_uint4(
        f2tf(v.x * rs * g.x), f2tf(v.y * rs * g.y),
        f2tf(v.z * rs * g.z), f2tf(v.w * rs * g.w));
}

// ---------------- TF32 tensor-core GEMM --------------------------------------
// C[M,1024] = A[M,1024] * B[1024,1024]; CTA tile 256x128, BK=32, 256 threads,
// 8 warps 4(m)x2(n), warp tile 64x64. cp.async double-buffered, tf32 inputs.
// modes: 0 = raw f32 out, 1 = tf32 out, 2 = rope+tf32 (K), 3 = rope+scale+tf32 (Q)
#define GM 256
#define GN 128
#define AST 36
#define BST 136
#define ABUF (GM * AST)        // 9216 words
#define BBUF (32 * BST)        // 4352 words
#define BUFW (ABUF + BBUF)     // 13568 words (54272 B per buffer)

__device__ __forceinline__ void tgemm_body(
    const uint32_t* __restrict__ A, const uint32_t* __restrict__ B,
    void* __restrict__ Cout, int mode, int bx, int by)
{
    extern __shared__ uint32_t sm[];
    int tid = threadIdx.x;
    int wid = tid >> 5, lane = tid & 31;
    int g = lane >> 2, tg = lane & 3;
    int warp_m = (wid & 3) * 64;
    int warp_n = (wid >> 2) * 64;

    const uint32_t* Ab = A + (size_t)by * GM * DIM;
    const uint32_t* Bb = B + bx * GN;
    int brow = tid >> 3, bcol = (tid & 7) * 16;

    uint32_t sbase = (uint32_t)__cvta_generic_to_shared(sm);
    uint32_t adst0 = sbase + (uint32_t)(tid * AST) * 4;
    uint32_t bdst0 = sbase + (uint32_t)(ABUF + brow * BST + bcol) * 4;
    const uint32_t BUFB = BUFW * 4;

    float acc[4][8][4];
    #pragma unroll
    for (int mt = 0; mt < 4; mt++)
        #pragma unroll
        for (int nt = 0; nt < 8; nt++)
            #pragma unroll
            for (int r = 0; r < 4; r++) acc[mt][nt][r] = 0.f;

    // stage 0
    {
        const uint32_t* as = Ab + (size_t)tid * DIM;
        #pragma unroll
        for (int c = 0; c < 8; c++) cpa(adst0 + 16 * c, as + 4 * c);
        const uint32_t* bs = Bb + (size_t)brow * DIM + bcol;
        #pragma unroll
        for (int c = 0; c < 4; c++) cpa(bdst0 + 16 * c, bs + 4 * c);
    }
    cpcommit();

    for (int kt = 0; kt < DIM / 32; kt++) {
        if (kt < DIM / 32 - 1) {
            int k0 = (kt + 1) * 32;
            uint32_t off = ((kt + 1) & 1) * BUFB;
            const uint32_t* as = Ab + (size_t)tid * DIM + k0;
            #pragma unroll
            for (int c = 0; c < 8; c++) cpa(adst0 + off + 16 * c, as + 4 * c);
            const uint32_t* bs = Bb + (size_t)(k0 + brow) * DIM + bcol;
            #pragma unroll
            for (int c = 0; c < 4; c++) cpa(bdst0 + off + 16 * c, bs + 4 * c);
            cpcommit();
            cpwait1();
        } else {
            cpwait0();
        }
        __syncthreads();

        const uint32_t* As = sm + (kt & 1) * BUFW;
        const uint32_t* Bs = As + ABUF;
        #pragma unroll
        for (int ks = 0; ks < 4; ks++) {
            int kk = ks * 8;
            uint32_t af[4][4];
            #pragma unroll
            for (int mt = 0; mt < 4; mt++) {
                int r0 = warp_m + mt * 16 + g;
                af[mt][0] = As[r0 * AST + kk + tg];
                af[mt][1] = As[(r0 + 8) * AST + kk + tg];
                af[mt][2] = As[r0 * AST + kk + tg + 4];
                af[mt][3] = As[(r0 + 8) * AST + kk + tg + 4];
            }
            #pragma unroll
            for (int nt = 0; nt < 8; nt++) {
                int nc = warp_n + nt * 8 + g;
                uint32_t bf[2];
                bf[0] = Bs[(kk + tg) * BST + nc];
                bf[1] = Bs[(kk + tg + 4) * BST + nc];
                #pragma unroll
                for (int mt = 0; mt < 4; mt++)
                    mma_tf32(acc[mt][nt], af[mt], bf);
            }
        }
        __syncthreads();
    }

    int row0b = by * GM + warp_m + g;
    int colb  = bx * GN + warp_n + 2 * tg;
    if (mode == 0) {
        float* C = (float*)Cout;
        #pragma unroll
        for (int mt = 0; mt < 4; mt++) {
            float* Cb = C + (size_t)(row0b + mt * 16) * DIM + colb;
            #pragma unroll
            for (int nt = 0; nt < 8; nt++) {
                *(float2*)(Cb + nt * 8) =
                    make_float2(acc[mt][nt][0], acc[mt][nt][1]);
                *(float2*)(Cb + (size_t)8 * DIM + nt * 8) =
                    make_float2(acc[mt][nt][2], acc[mt][nt][3]);
            }
        }
    } else {
        uint32_t* C = (uint32_t*)Cout;
        #pragma unroll
        for (int mt = 0; mt < 4; mt++) {
            int r0 = row0b + mt * 16, r1 = r0 + 8;
            int pos0 = r0 & (NSEQ - 1), pos1 = r1 & (NSEQ - 1);
            #pragma unroll
            for (int nt = 0; nt < 8; nt++) {
                int col = colb + nt * 8;
                float c0 = acc[mt][nt][0], c1 = acc[mt][nt][1];
                float c2 = acc[mt][nt][2], c3 = acc[mt][nt][3];
                if (mode >= 2) {
                    int p = (col & 63) >> 1;
                    float cs0 = g_cos[pos0 * 32 + p], sn0 = g_sin[pos0 * 32 + p];
                    float cs1 = g_cos[pos1 * 32 + p], sn1 = g_sin[pos1 * 32 + p];
                    float t0 = c0 * cs0 - c1 * sn0;
                    float t1 = c1 * cs0 + c0 * sn0;
                    float t2 = c2 * cs1 - c3 * sn1;
                    float t3 = c3 * cs1 + c2 * sn1;
                    c0 = t0; c1 = t1; c2 = t2; c3 = t3;
                    if (mode == 3) {
                        c0 *= 0.125f; c1 *= 0.125f; c2 *= 0.125f; c3 *= 0.125f;
                    }
                }
                *(uint2*)(C + (size_t)r0 * DIM + col) = make_uint2(f2tf(c0), f2tf(c1));
                *(uint2*)(C + (size_t)r1 * DIM + col) = make_uint2(f2tf(c2), f2tf(c3));
            }
        }
    }
}

// Batched QKV projections: z=0 -> Q (rope+scale), z=1..3 -> K[i] (rope), z=4..6 -> V[i]
__global__ __launch_bounds__(256) void tgemm7_kernel(const uint32_t* __restrict__ A)
{
    int z = blockIdx.z;
    const uint32_t* B;
    void* C;
    int mode;
    if (z == 0)      { B = g_wq;                              C = g_q;      mode = 3; }
    else if (z < 4)  { B = g_wk + (size_t)(z - 1) * DIM * DIM; C = g_k[z - 1]; mode = 2; }
    else             { B = g_wv + (size_t)(z - 4) * DIM * DIM; C = g_v[z - 4]; mode = 1; }
    tgemm_body(A, B, C, mode, blockIdx.x, blockIdx.y);
}

__global__ __launch_bounds__(256) void tgemmo_kernel(
    const uint32_t* __restrict__ A, float* __restrict__ C)
{
    tgemm_body(A, g_wo, C, 0, blockIdx.x, blockIdx.y);
}

// ---------------- Tensor-core causal flash attention -------------------------
// All inputs pre-rotated tf32. grid (16,16,4) with qb REVERSED (heavy first),
// 128 threads (4 warps), warp w owns query rows [16w,16w+16).
#define SQT 68

__global__ __launch_bounds__(128) void attn_mma_kernel(
    const uint32_t* __restrict__ Qg, const uint32_t* __restrict__ Kg,
    const uint32_t* __restrict__ Vg, uint32_t* __restrict__ Og, int last)
{
    extern __shared__ uint32_t smu[];
    uint32_t* QPs = smu;                  // 64 x SQT : Q, later P
    uint32_t* Ks  = smu + 64 * SQT;
    uint32_t* Vs  = smu + 2 * 64 * SQT;

    int qb = (gridDim.x - 1) - blockIdx.x;     // heavy CTAs first
    int h = blockIdx.y, b = blockIdx.z;
    int tid = threadIdx.x;
    int wid = tid >> 5, lane = tid & 31;
    int g = lane >> 2, tg = lane & 3;
    int qrow = wid * 16;
    int q0 = qb * 64;
    size_t base = ((size_t)b * NSEQ) * DIM + h * DH;

    uint32_t sbase = (uint32_t)__cvta_generic_to_shared(smu);
    int srow = tid >> 1;                  // 0..63
    int shalf = (tid & 1) * 32;           // word offset within row
    uint32_t rowdst = sbase + (uint32_t)(srow * SQT + shalf) * 4;

    // ---- stage Q tile (pre-rotated, pre-scaled tf32) ----
    {
        const uint32_t* src = Qg + base + (size_t)(q0 + srow) * DIM + shalf;
        #pragma unroll
        for (int c = 0; c < 8; c++) cpa(rowdst + 16 * c, src + 4 * c);
    }
    cpcommit(); cpwait0();
    __syncthreads();

    // ---- preload Q fragments ----
    uint32_t qa[8][4];
    #pragma unroll
    for (int kt = 0; kt < 8; kt++) {
        qa[kt][0] = QPs[(qrow + g)     * SQT + kt * 8 + tg];
        qa[kt][1] = QPs[(qrow + g + 8) * SQT + kt * 8 + tg];
        qa[kt][2] = QPs[(qrow + g)     * SQT + kt * 8 + tg + 4];
        qa[kt][3] = QPs[(qrow + g + 8) * SQT + kt * 8 + tg + 4];
    }

    float m0 = -INFINITY, m1 = -INFINITY, l0 = 0.f, l1 = 0.f;
    float oacc[8][4];
    #pragma unroll
    for (int nt = 0; nt < 8; nt++)
        #pragma unroll
        for (int r = 0; r < 4; r++) oacc[nt][r] = 0.f;

    int aq0 = q0 + qrow + g;
    int aq1 = aq0 + 8;
    uint32_t kdst = rowdst + (uint32_t)(64 * SQT) * 4;
    uint32_t vdst = rowdst + (uint32_t)(2 * 64 * SQT) * 4;

    for (int kb = 0; kb <= qb; kb++) {
        int k0 = kb * 64;
        __syncthreads();   // previous PV done before overwriting K/V
        {
            const uint32_t* ks = Kg + base + (size_t)(k0 + srow) * DIM + shalf;
            const uint32_t* vs = Vg + base + (size_t)(k0 + srow) * DIM + shalf;
            #pragma unroll
            for (int c = 0; c < 8; c++) cpa(kdst + 16 * c, ks + 4 * c);
            #pragma unroll
            for (int c = 0; c < 8; c++) cpa(vdst + 16 * c, vs + 4 * c);
        }
        cpcommit(); cpwait0();
        __syncthreads();

        // ---- S = Q K^T ----
        float S[8][4];
        #pragma unroll
        for (int nt = 0; nt < 8; nt++)
            #pragma unroll
            for (int r = 0; r < 4; r++) S[nt][r] = 0.f;
        #pragma unroll
        for (int kt = 0; kt < 8; kt++) {
            #pragma unroll
            for (int nt = 0; nt < 8; nt++) {
                uint32_t bf[2];
                bf[0] = Ks[(nt * 8 + g) * SQT + kt * 8 + tg];
                bf[1] = Ks[(nt * 8 + g) * SQT + kt * 8 + tg + 4];
                mma_tf32(S[nt], qa[kt], bf);
            }
        }

        // ---- causal mask on diagonal block ----
        if (kb == qb) {
            #pragma unroll
            for (int nt = 0; nt < 8; nt++) {
                int c0 = k0 + nt * 8 + 2 * tg;
                if (c0 > aq0)     S[nt][0] = -INFINITY;
                if (c0 + 1 > aq0) S[nt][1] = -INFINITY;
                if (c0 > aq1)     S[nt][2] = -INFINITY;
                if (c0 + 1 > aq1) S[nt][3] = -INFINITY;
            }
        }

        // ---- online softmax ----
        float rm0 = -INFINITY, rm1 = -INFINITY;
        #pragma unroll
        for (int nt = 0; nt < 8; nt++) {
            rm0 = fmaxf(rm0, fmaxf(S[nt][0], S[nt][1]));
            rm1 = fmaxf(rm1, fmaxf(S[nt][2], S[nt][3]));
        }
        #pragma unroll
        for (int o = 1; o <= 2; o <<= 1) {
            rm0 = fmaxf(rm0, __shfl_xor_sync(0xffffffffu, rm0, o));
            rm1 = fmaxf(rm1, __shfl_xor_sync(0xffffffffu, rm1, o));
        }
        float mn0 = fmaxf(m0, rm0), mn1 = fmaxf(m1, rm1);
        float cor0 = __expf(m0 - mn0), cor1 = __expf(m1 - mn1);
        m0 = mn0; m1 = mn1;
        float rs0 = 0.f, rs1 = 0.f;
        #pragma unroll
        for (int nt = 0; nt < 8; nt++) {
            float p0 = __expf(S[nt][0] - mn0);
            float p1 = __expf(S[nt][1] - mn0);
            float p2 = __expf(S[nt][2] - mn1);
            float p3 = __expf(S[nt][3] - mn1);
            rs0 += p0 + p1; rs1 += p2 + p3;
            *(uint2*)&QPs[(qrow + g)     * SQT + nt * 8 + 2 * tg] =
                make_uint2(f2tf(p0), f2tf(p1));
            *(uint2*)&QPs[(qrow + g + 8) * SQT + nt * 8 + 2 * tg] =
                make_uint2(f2tf(p2), f2tf(p3));
        }
        #pragma unroll
        for (int o = 1; o <= 2; o <<= 1) {
            rs0 += __shfl_xor_sync(0xffffffffu, rs0, o);
            rs1 += __shfl_xor_sync(0xffffffffu, rs1, o);
        }
        l0 = l0 * cor0 + rs0;
        l1 = l1 * cor1 + rs1;
        #pragma unroll
        for (int nt = 0; nt < 8; nt++) {
            oacc[nt][0] *= cor0; oacc[nt][1] *= cor0;
            oacc[nt][2] *= cor1; oacc[nt][3] *= cor1;
        }
        __syncwarp();

        // ---- O += P V ----
        #pragma unroll
        for (int kt = 0; kt < 8; kt++) {
            uint32_t pa[4];
            pa[0] = QPs[(qrow + g)     * SQT + kt * 8 + tg];
            pa[1] = QPs[(qrow + g + 8) * SQT + kt * 8 + tg];
            pa[2] = QPs[(qrow + g)     * SQT + kt * 8 + tg + 4];
            pa[3] = QPs[(qrow + g + 8) * SQT + kt * 8 + tg + 4];
            #pragma unroll
            for (int nt = 0; nt < 8; nt++) {
                uint32_t bf[2];
                bf[0] = Vs[(kt * 8 + tg)     * SQT + nt * 8 + g];
                bf[1] = Vs[(kt * 8 + tg + 4) * SQT + nt * 8 + g];
                mma_tf32(oacc[nt], pa, bf);
            }
        }
    }

    // ---- normalize; intermediate: SiLU + RoPE + scale (next layer's Q); tf32 out
    float inv0 = 1.0f / l0, inv1 = 1.0f / l1;
    uint32_t* d0 = Og + base + (size_t)aq0 * DIM + 2 * tg;
    uint32_t* d1 = Og + base + (size_t)aq1 * DIM + 2 * tg;
    #pragma unroll
    for (int nt = 0; nt < 8; nt++) {
        float v0 = oacc[nt][0] * inv0, v1 = oacc[nt][1] * inv0;
        float v2 = oacc[nt][2] * inv1, v3 = oacc[nt][3] * inv1;
        if (!last) {
            v0 = v0 / (1.0f + __expf(-v0));
            v1 = v1 / (1.0f + __expf(-v1));
            v2 = v2 / (1.0f + __expf(-v2));
            v3 = v3 / (1.0f + __expf(-v3));
            int p = nt * 4 + tg;
            float cs0 = g_cos[aq0 * 32 + p], sn0 = g_sin[aq0 * 32 + p];
            float cs1 = g_cos[aq1 * 32 + p], sn1 = g_sin[aq1 * 32 + p];
            float t0 = (v0 * cs0 - v1 * sn0) * 0.125f;
            float t1 = (v1 * cs0 + v0 * sn0) * 0.125f;
            float t2 = (v2 * cs1 - v3 * sn1) * 0.125f;
            float t3 = (v3 * cs1 + v2 * sn1) * 0.125f;
            v0 = t0; v1 = t1; v2 = t2; v3 = t3;
        }
        *(uint2*)(d0 + nt * 8) = make_uint2(f2tf(v0), f2tf(v1));
        *(uint2*)(d1 + nt * 8) = make_uint2(f2tf(v2), f2tf(v3));
    }
}

// ---------------- launch ------------------------------------------------------
extern "C" void kernel_launch(void* const* d_in, const int* in_sizes, int n_in,
                              void* d_out, int out_size)
{
    const float* tokens = (const float*)d_in[0];
    const float* gamma  = (const float*)d_in[1];
    const float* Wq     = (const float*)d_in[2];
    const float* Wk     = (const float*)d_in[3];
    const float* Wv     = (const float*)d_in[4];
    const float* Wo     = (const float*)d_in[5];
    float* out = (float*)d_out;

    uint32_t *xnt, *q, *pa, *pb, *kb, *vb, *wq, *wk, *wv, *wo;
    cudaGetSymbolAddress((void**)&xnt, g_xnt);
    cudaGetSymbolAddress((void**)&q,   g_q);
    cudaGetSymbolAddress((void**)&pa,  g_pa);
    cudaGetSymbolAddress((void**)&pb,  g_pb);
    cudaGetSymbolAddress((void**)&kb,  g_k);
    cudaGetSymbolAddress((void**)&vb,  g_v);
    cudaGetSymbolAddress((void**)&wq,  g_wq);
    cudaGetSymbolAddress((void**)&wk,  g_wk);
    cudaGetSymbolAddress((void**)&wv,  g_wv);
    cudaGetSymbolAddress((void**)&wo,  g_wo);

    const size_t SZ = (size_t)MROWS * DIM;

    rope_tables_kernel<<<(NSEQ * 32 + 255) / 256, 256>>>();
    rmsnorm_kernel<<<MROWS, 256>>>(tokens, gamma, xnt);
    wconv_kernel<<<(DIM * DIM / 4 + 255) / 256, 256>>>(Wq, wq, DIM * DIM / 4);
    wconv_kernel<<<(NLAYER * DIM * DIM / 4 + 255) / 256, 256>>>(Wk, wk, NLAYER * DIM * DIM / 4);
    wconv_kernel<<<(NLAYER * DIM * DIM / 4 + 255) / 256, 256>>>(Wv, wv, NLAYER * DIM * DIM / 4);
    wconv_kernel<<<(DIM * DIM / 4 + 255) / 256, 256>>>(Wo, wo, DIM * DIM / 4);

    size_t gsm = (size_t)2 * BUFW * sizeof(uint32_t);   // 108,544 B
    cudaFuncSetAttribute(tgemm7_kernel,
                         cudaFuncAttributeMaxDynamicSharedMemorySize, (int)gsm);
    cudaFuncSetAttribute(tgemmo_kernel,
                         cudaFuncAttributeMaxDynamicSharedMemorySize, (int)gsm);

    dim3 g7(DIM / GN, MROWS / GM, 7);     // (8,16,7)
    tgemm7_kernel<<<g7, 256, gsm>>>(xnt);

    size_t asm_ = (size_t)3 * 64 * SQT * sizeof(uint32_t);   // 52,224 B
    cudaFuncSetAttribute(attn_mma_kernel,
                         cudaFuncAttributeMaxDynamicSharedMemorySize, (int)asm_);
    dim3 ga(NSEQ / 64, NHEAD, 4);
    attn_mma_kernel<<<ga, 128, asm_>>>(q,  kb,          vb,          pa, 0);
    attn_mma_kernel<<<ga, 128, asm_>>>(pa, kb + SZ,     vb + SZ,     pb, 0);
    attn_mma_kernel<<<ga, 128, asm_>>>(pb, kb + 2 * SZ, vb + 2 * SZ, pa, 1);

    dim3 gg(DIM / GN, MROWS / GM);        // (8,16)
    tgemmo_kernel<<<gg, 256, gsm>>>(pa, out);
}